// round 16
// baseline (speedup 1.0000x reference)
#include <cuda_runtime.h>
#include <cuda_bf16.h>
#include <cstdint>

// Problem shape: B=16, N=1024, C=1280, d=160
#define SZ_B   16
#define SZ_N   1024
#define SZ_C   1280
#define SZ_D   160
#define SZ_BN  (SZ_B * SZ_N)

typedef __nv_bfloat16 bf16;

// ---------------------------------------------------------------------------
// Scratch (static __device__ globals)
// ---------------------------------------------------------------------------
__device__ float g_s  [(size_t)SZ_B * SZ_N * SZ_N];
__device__ float g_s2 [(size_t)SZ_B * SZ_C * SZ_C];
__device__ float g_pav[(size_t)SZ_BN * SZ_C];
__device__ float g_m2 [(size_t)SZ_B * SZ_C];
__device__ float g_i2 [(size_t)SZ_B * SZ_C];

__device__ bf16 g_xh  [(size_t)SZ_BN * SZ_C];
__device__ bf16 g_xl  [(size_t)SZ_BN * SZ_C];
__device__ bf16 g_xth [(size_t)SZ_B * SZ_C * SZ_N];
__device__ bf16 g_xtl [(size_t)SZ_B * SZ_C * SZ_N];
__device__ bf16 g_wkqth[(size_t)2 * SZ_D * SZ_C];
__device__ bf16 g_wkqtl[(size_t)2 * SZ_D * SZ_C];
__device__ bf16 g_wvth[(size_t)SZ_C * SZ_C];
__device__ bf16 g_wvtl[(size_t)SZ_C * SZ_C];
__device__ bf16 g_kqh [(size_t)SZ_BN * 2 * SZ_D];
__device__ bf16 g_kql [(size_t)SZ_BN * 2 * SZ_D];
__device__ bf16 g_vth [(size_t)SZ_C * SZ_BN];
__device__ bf16 g_vtl [(size_t)SZ_C * SZ_BN];
__device__ bf16 g_ph  [(size_t)SZ_B * SZ_N * SZ_N];
__device__ bf16 g_pl  [(size_t)SZ_B * SZ_N * SZ_N];
__device__ bf16 g_p2th[(size_t)SZ_B * SZ_C * SZ_C];
__device__ bf16 g_p2tl[(size_t)SZ_B * SZ_C * SZ_C];

// ---------------------------------------------------------------------------
// PTX helpers
// ---------------------------------------------------------------------------
__device__ __forceinline__ uint32_t smem_u32(const void* p) {
    uint32_t a;
    asm("{ .reg .u64 t; cvta.to.shared.u64 t, %1; cvt.u32.u64 %0, t; }"
        : "=r"(a) : "l"(p));
    return a;
}
#define SWZ128(off) ((off) ^ (((off) >> 3) & 0x70))

__device__ __forceinline__ void ldsm4(uint32_t& a0, uint32_t& a1, uint32_t& a2,
                                      uint32_t& a3, uint32_t addr) {
    asm volatile("ldmatrix.sync.aligned.m8n8.x4.shared.b16 {%0,%1,%2,%3}, [%4];"
                 : "=r"(a0), "=r"(a1), "=r"(a2), "=r"(a3) : "r"(addr));
}
__device__ __forceinline__ void mma16816(float* c, const uint32_t* a,
                                         const uint32_t* b) {
    asm volatile(
        "mma.sync.aligned.m16n8k16.row.col.f32.bf16.bf16.f32 "
        "{%0,%1,%2,%3}, {%4,%5,%6,%7}, {%8,%9}, {%0,%1,%2,%3};"
        : "+f"(c[0]), "+f"(c[1]), "+f"(c[2]), "+f"(c[3])
        : "r"(a[0]), "r"(a[1]), "r"(a[2]), "r"(a[3]), "r"(b[0]), "r"(b[1]));
}
__device__ __forceinline__ void cp16(uint32_t dst, const void* src, int sz) {
    asm volatile("cp.async.cg.shared.global [%0], [%1], 16, %2;"
                 :: "r"(dst), "l"(src), "r"(sz));
}
#define CP_COMMIT() asm volatile("cp.async.commit_group;" ::: "memory")

__device__ __forceinline__ uint32_t pack_hi(float a, float b) {
    __nv_bfloat162 h; h.x = __float2bfloat16(a); h.y = __float2bfloat16(b);
    return *reinterpret_cast<uint32_t*>(&h);
}
__device__ __forceinline__ uint32_t pack_lo(float a, float b) {
    const bf16 ha = __float2bfloat16(a), hb = __float2bfloat16(b);
    __nv_bfloat162 l;
    l.x = __float2bfloat16(a - __bfloat162float(ha));
    l.y = __float2bfloat16(b - __bfloat162float(hb));
    return *reinterpret_cast<uint32_t*>(&l);
}

#define T_BYTES 16384

// ===========================================================================
// Narrow GEMM: 128x128 tile, 3-stage (for kq, s, and symmetric s2)
// ===========================================================================
#define STG     65536
#define STAGES  3

template <int OM, bool SYM>
__global__ __launch_bounds__(256, 1)
void gemm_hl(const bf16* __restrict__ Ah, const bf16* __restrict__ Al,
             const bf16* __restrict__ Bh, const bf16* __restrict__ Bl,
             float* __restrict__ Cf, bf16* __restrict__ Ch, bf16* __restrict__ Cl,
             int Ncols, int K, int lda, int ldb, int ldc,
             long sA, long sB, long sC)
{
    extern __shared__ char smem[];
    Ah += (long)blockIdx.z * sA;  Al += (long)blockIdx.z * sA;
    Bh += (long)blockIdx.z * sB;  Bl += (long)blockIdx.z * sB;
    if (OM == 0) Cf += (long)blockIdx.z * sC;
    if (OM == 1) { Ch += (long)blockIdx.z * sC; Cl += (long)blockIdx.z * sC; }

    const int tid  = threadIdx.x;
    const int lane = tid & 31;
    const int wid  = tid >> 5;
    const int wm   = wid & 1;
    const int wn   = wid >> 1;

    int bx, by;
    if (SYM) {
        int t = blockIdx.x, b = 0;
        while ((b + 1) * (b + 2) / 2 <= t) b++;
        by = b; bx = t - b * (b + 1) / 2;
    } else { bx = blockIdx.x; by = blockIdx.y; }
    const int m0 = by * 128;
    const int n0 = bx * 128;

    const uint32_t sb = smem_u32(smem);
    const int nch = (K + 63) / 64;

    const int gc = tid & 7;
    uint32_t swz[4];
    const bf16 *pA[4], *pB[4];
    int szB[4];
    const long dAl = Al - Ah;
    const long dBl = Bl - Bh;
#pragma unroll
    for (int j = 0; j < 4; j++) {
        const int row = (tid >> 3) + j * 32;
        swz[j] = SWZ128((uint32_t)(row * 128 + gc * 16));
        pA[j] = Ah + (long)(m0 + row) * lda + gc * 8;
        pB[j] = Bh + (long)(n0 + row) * ldb + gc * 8;
        szB[j] = (n0 + row < Ncols) ? 16 : 0;
    }
    auto issue_stage = [&](int ch, int buf) {
        const int k0 = ch * 64;
        const uint32_t base = sb + buf * STG;
        const int kv = (k0 + gc * 8 < K) ? 16 : 0;
#pragma unroll
        for (int j = 0; j < 4; j++) {
            cp16(base + swz[j],               pA[j] + k0,       kv);
            cp16(base + T_BYTES + swz[j],     pA[j] + dAl + k0, kv);
            cp16(base + 2 * T_BYTES + swz[j], pB[j] + k0,       szB[j] & kv);
            cp16(base + 3 * T_BYTES + swz[j], pB[j] + dBl + k0, szB[j] & kv);
        }
        CP_COMMIT();
    };

    float acc[4][4][4];
#pragma unroll
    for (int i = 0; i < 4; i++)
#pragma unroll
        for (int j = 0; j < 4; j++)
#pragma unroll
            for (int u = 0; u < 4; u++) acc[i][j][u] = 0.f;

    for (int st = 0; st < STAGES && st < nch; st++) issue_stage(st, st);

    const int r8 = lane & 7;
    const int bhalf = (lane >> 3) & 1;
    const int bpair = (lane >> 4) & 1;
    const int g2 = lane >> 3;

    for (int ch = 0; ch < nch; ch++) {
        int pend = nch - 1 - ch;
        if (pend > STAGES - 1) pend = STAGES - 1;
        if (pend == 0)      asm volatile("cp.async.wait_group 0;" ::: "memory");
        else if (pend == 1) asm volatile("cp.async.wait_group 1;" ::: "memory");
        else                asm volatile("cp.async.wait_group 2;" ::: "memory");
        __syncthreads();

        const uint32_t aBh = sb + (ch % STAGES) * STG;
        const uint32_t aBl = aBh + T_BYTES;
        const uint32_t bBh = aBh + 2 * T_BYTES;
        const uint32_t bBl = aBh + 3 * T_BYTES;

#pragma unroll
        for (int kt = 0; kt < 4; kt++) {
            uint32_t bh[4][2], bl[4][2];
#pragma unroll
            for (int ntp = 0; ntp < 2; ntp++) {
                const int brow = wn * 32 + (ntp * 2 + bpair) * 8 + r8;
                const uint32_t boff =
                    SWZ128((uint32_t)(brow * 128 + (2 * kt + bhalf) * 16));
                ldsm4(bh[ntp * 2][0], bh[ntp * 2][1],
                      bh[ntp * 2 + 1][0], bh[ntp * 2 + 1][1], bBh + boff);
                ldsm4(bl[ntp * 2][0], bl[ntp * 2][1],
                      bl[ntp * 2 + 1][0], bl[ntp * 2 + 1][1], bBl + boff);
            }
#pragma unroll
            for (int mt = 0; mt < 4; mt++) {
                const int arow = wm * 64 + mt * 16 + (g2 & 1) * 8 + r8;
                const uint32_t aoff =
                    SWZ128((uint32_t)(arow * 128 + (2 * kt + (g2 >> 1)) * 16));
                uint32_t ah[4], al[4];
                ldsm4(ah[0], ah[1], ah[2], ah[3], aBh + aoff);
                ldsm4(al[0], al[1], al[2], al[3], aBl + aoff);
#pragma unroll
                for (int nt = 0; nt < 4; nt++) {
                    mma16816(acc[mt][nt], ah, bh[nt]);
                    mma16816(acc[mt][nt], ah, bl[nt]);
                    mma16816(acc[mt][nt], al, bh[nt]);
                }
            }
        }
        __syncthreads();
        if (ch + STAGES < nch) issue_stage(ch + STAGES, ch % STAGES);
    }

#pragma unroll
    for (int mt = 0; mt < 4; mt++) {
#pragma unroll
        for (int nt = 0; nt < 4; nt++) {
            const int row0 = m0 + wm * 64 + mt * 16 + (lane >> 2);
            const int col  = n0 + wn * 32 + nt * 8 + (lane & 3) * 2;
            if (col >= Ncols) continue;
            const long o0 = (long)row0 * ldc + col;
            const long o1 = (long)(row0 + 8) * ldc + col;
            if (OM == 0) {
                *reinterpret_cast<float2*>(Cf + o0) =
                    make_float2(acc[mt][nt][0], acc[mt][nt][1]);
                *reinterpret_cast<float2*>(Cf + o1) =
                    make_float2(acc[mt][nt][2], acc[mt][nt][3]);
            } else {
                *reinterpret_cast<uint32_t*>(Ch + o0) =
                    pack_hi(acc[mt][nt][0], acc[mt][nt][1]);
                *reinterpret_cast<uint32_t*>(Cl + o0) =
                    pack_lo(acc[mt][nt][0], acc[mt][nt][1]);
                *reinterpret_cast<uint32_t*>(Ch + o1) =
                    pack_hi(acc[mt][nt][2], acc[mt][nt][3]);
                *reinterpret_cast<uint32_t*>(Cl + o1) =
                    pack_lo(acc[mt][nt][2], acc[mt][nt][3]);
            }
        }
    }

    if (SYM && bx != by) {
        __syncthreads();
        float* T = reinterpret_cast<float*>(smem);
#pragma unroll
        for (int mt = 0; mt < 4; mt++) {
#pragma unroll
            for (int nt = 0; nt < 4; nt++) {
                const int r0 = wm * 64 + mt * 16 + (lane >> 2);
                const int c  = wn * 32 + nt * 8 + (lane & 3) * 2;
                T[(c)     * 128 + r0]     = acc[mt][nt][0];
                T[(c + 1) * 128 + r0]     = acc[mt][nt][1];
                T[(c)     * 128 + r0 + 8] = acc[mt][nt][2];
                T[(c + 1) * 128 + r0 + 8] = acc[mt][nt][3];
            }
        }
        __syncthreads();
        for (int idx = tid; idx < 128 * 32; idx += 256) {
            const int row = idx >> 5, c4 = idx & 31;
            const float4 v = reinterpret_cast<const float4*>(T + row * 128)[c4];
            *reinterpret_cast<float4*>(Cf + (long)(n0 + row) * ldc + m0 + c4 * 4) = v;
        }
    }
}

// ===========================================================================
// Wide GEMM: 128x256 tile, 2-stage (for vT, pav, final). N % 256 == 0, K % 64 == 0.
//   OM=0: fp32 out   OM=1: bf16 hi/lo out   OM=2: fused final epilogue
// ===========================================================================
#define B_BYTES_W 32768
#define STG_W     98304     // A(16K)+A(16K)+B(32K)+B(32K)
#define STAGES_W  2

template <int OM>
__global__ __launch_bounds__(256, 1)
void gemm_wide(const bf16* __restrict__ Ah, const bf16* __restrict__ Al,
               const bf16* __restrict__ Bh, const bf16* __restrict__ Bl,
               float* __restrict__ Cf, bf16* __restrict__ Ch, bf16* __restrict__ Cl,
               const float* __restrict__ Pv, const float* __restrict__ Xr,
               const float* __restrict__ gamma, const float* __restrict__ beta,
               int K, int lda, int ldb, int ldc, long sA, long sB, long sC)
{
    extern __shared__ char smem[];
    Ah += (long)blockIdx.z * sA;  Al += (long)blockIdx.z * sA;
    Bh += (long)blockIdx.z * sB;  Bl += (long)blockIdx.z * sB;
    if (OM == 0) Cf += (long)blockIdx.z * sC;
    if (OM == 1) { Ch += (long)blockIdx.z * sC; Cl += (long)blockIdx.z * sC; }
    if (OM == 2) { Cf += (long)blockIdx.z * sC; Pv += (long)blockIdx.z * sC;
                   Xr += (long)blockIdx.z * sC; }

    const int tid  = threadIdx.x;
    const int lane = tid & 31;
    const int wid  = tid >> 5;
    const int wm   = wid & 1;        // 2 warp rows (64)
    const int wn   = wid >> 1;       // 4 warp cols (64)
    const int m0   = blockIdx.y * 128;
    const int n0   = blockIdx.x * 256;

    const uint32_t sb = smem_u32(smem);
    const int nch = K / 64;

    // hoisted staging: A 4 rows/thread, B 8 rows/thread
    const int gc = tid & 7;
    const int rb = tid >> 3;
    uint32_t swzA[4], swzB[8];
    const bf16 *pA[4], *pB[8];
    const long dAl = Al - Ah;
    const long dBl = Bl - Bh;
#pragma unroll
    for (int j = 0; j < 4; j++) {
        const int row = rb + j * 32;
        swzA[j] = SWZ128((uint32_t)(row * 128 + gc * 16));
        pA[j] = Ah + (long)(m0 + row) * lda + gc * 8;
    }
#pragma unroll
    for (int j = 0; j < 8; j++) {
        const int row = rb + j * 32;
        swzB[j] = SWZ128((uint32_t)(row * 128 + gc * 16));
        pB[j] = Bh + (long)(n0 + row) * ldb + gc * 8;
    }
    auto issue_stage = [&](int ch, int buf) {
        const int k0 = ch * 64;
        const uint32_t base = sb + buf * STG_W;
#pragma unroll
        for (int j = 0; j < 4; j++) {
            cp16(base + swzA[j],           pA[j] + k0,       16);
            cp16(base + T_BYTES + swzA[j], pA[j] + dAl + k0, 16);
        }
        const uint32_t bbase = base + 2 * T_BYTES;
#pragma unroll
        for (int j = 0; j < 8; j++) {
            cp16(bbase + swzB[j],             pB[j] + k0,       16);
            cp16(bbase + B_BYTES_W + swzB[j], pB[j] + dBl + k0, 16);
        }
        CP_COMMIT();
    };

    float acc[4][8][4];
#pragma unroll
    for (int i = 0; i < 4; i++)
#pragma unroll
        for (int j = 0; j < 8; j++)
#pragma unroll
            for (int u = 0; u < 4; u++) acc[i][j][u] = 0.f;

    issue_stage(0, 0);
    if (nch > 1) issue_stage(1, 1);

    const int r8 = lane & 7;
    const int bhalf = (lane >> 3) & 1;
    const int bpair = (lane >> 4) & 1;
    const int g2 = lane >> 3;

    for (int ch = 0; ch < nch; ch++) {
        if (ch + 1 < nch) asm volatile("cp.async.wait_group 1;" ::: "memory");
        else              asm volatile("cp.async.wait_group 0;" ::: "memory");
        __syncthreads();

        const uint32_t aBh = sb + (ch & 1) * STG_W;
        const uint32_t aBl = aBh + T_BYTES;
        const uint32_t bBh = aBh + 2 * T_BYTES;
        const uint32_t bBl = bBh + B_BYTES_W;

#pragma unroll
        for (int kt = 0; kt < 4; kt++) {
            uint32_t bh[8][2], bl[8][2];
#pragma unroll
            for (int ntp = 0; ntp < 4; ntp++) {
                const int brow = wn * 64 + (ntp * 2 + bpair) * 8 + r8;
                const uint32_t boff =
                    SWZ128((uint32_t)(brow * 128 + (2 * kt + bhalf) * 16));
                ldsm4(bh[ntp * 2][0], bh[ntp * 2][1],
                      bh[ntp * 2 + 1][0], bh[ntp * 2 + 1][1], bBh + boff);
                ldsm4(bl[ntp * 2][0], bl[ntp * 2][1],
                      bl[ntp * 2 + 1][0], bl[ntp * 2 + 1][1], bBl + boff);
            }
#pragma unroll
            for (int mt = 0; mt < 4; mt++) {
                const int arow = wm * 64 + mt * 16 + (g2 & 1) * 8 + r8;
                const uint32_t aoff =
                    SWZ128((uint32_t)(arow * 128 + (2 * kt + (g2 >> 1)) * 16));
                uint32_t ah[4], al[4];
                ldsm4(ah[0], ah[1], ah[2], ah[3], aBh + aoff);
                ldsm4(al[0], al[1], al[2], al[3], aBl + aoff);
#pragma unroll
                for (int nt = 0; nt < 8; nt++) {
                    mma16816(acc[mt][nt], ah, bh[nt]);
                    mma16816(acc[mt][nt], ah, bl[nt]);
                    mma16816(acc[mt][nt], al, bh[nt]);
                }
            }
        }
        __syncthreads();
        if (ch + 2 < nch) issue_stage(ch + 2, ch & 1);
    }

    float gv = 0.f, bv = 0.f;
    if (OM == 2) { gv = __ldg(gamma); bv = __ldg(beta); }

#pragma unroll
    for (int mt = 0; mt < 4; mt++) {
#pragma unroll
        for (int nt = 0; nt < 8; nt++) {
            const int row0 = m0 + wm * 64 + mt * 16 + (lane >> 2);
            const int col  = n0 + wn * 64 + nt * 8 + (lane & 3) * 2;
            const long o0 = (long)row0 * ldc + col;
            const long o1 = (long)(row0 + 8) * ldc + col;
            if (OM == 0) {
                *reinterpret_cast<float2*>(Cf + o0) =
                    make_float2(acc[mt][nt][0], acc[mt][nt][1]);
                *reinterpret_cast<float2*>(Cf + o1) =
                    make_float2(acc[mt][nt][2], acc[mt][nt][3]);
            } else if (OM == 1) {
                *reinterpret_cast<uint32_t*>(Ch + o0) =
                    pack_hi(acc[mt][nt][0], acc[mt][nt][1]);
                *reinterpret_cast<uint32_t*>(Cl + o0) =
                    pack_lo(acc[mt][nt][0], acc[mt][nt][1]);
                *reinterpret_cast<uint32_t*>(Ch + o1) =
                    pack_hi(acc[mt][nt][2], acc[mt][nt][3]);
                *reinterpret_cast<uint32_t*>(Cl + o1) =
                    pack_lo(acc[mt][nt][2], acc[mt][nt][3]);
            } else {
                const float2 p0 = *reinterpret_cast<const float2*>(Pv + o0);
                const float2 x0 = *reinterpret_cast<const float2*>(Xr + o0);
                const float2 p1 = *reinterpret_cast<const float2*>(Pv + o1);
                const float2 x1 = *reinterpret_cast<const float2*>(Xr + o1);
                *reinterpret_cast<float2*>(Cf + o0) = make_float2(
                    gv * p0.x + bv * acc[mt][nt][0] + 2.f * x0.x,
                    gv * p0.y + bv * acc[mt][nt][1] + 2.f * x0.y);
                *reinterpret_cast<float2*>(Cf + o1) = make_float2(
                    gv * p1.x + bv * acc[mt][nt][2] + 2.f * x1.x,
                    gv * p1.y + bv * acc[mt][nt][3] + 2.f * x1.y);
            }
        }
    }
}

// ---------------------------------------------------------------------------
// xprep: single read of x -> xh/xl + xth/xtl
// ---------------------------------------------------------------------------
__global__ void xprep(const float* __restrict__ x,
                      bf16* __restrict__ xh, bf16* __restrict__ xl,
                      bf16* __restrict__ xth, bf16* __restrict__ xtl)
{
    __shared__ float t[32][66];
    const int b = blockIdx.z;
    const int n0 = blockIdx.y * 32;
    const int c0 = blockIdx.x * 64;
    const int tid = threadIdx.x;
    const int tx = tid & 31, ty = tid >> 5;
    const float* xb = x + (long)b * SZ_N * SZ_C;
    bf16* xhb = xh + (long)b * SZ_N * SZ_C;
    bf16* xlb = xl + (long)b * SZ_N * SZ_C;
    bf16* xthb = xth + (long)b * SZ_C * SZ_N;
    bf16* xtlb = xtl + (long)b * SZ_C * SZ_N;

#pragma unroll
    for (int i = 0; i < 32; i += 8) {
        const int r = n0 + ty + i;
        const int c = c0 + tx * 2;
        const float2 v = *reinterpret_cast<const float2*>(xb + (long)r * SZ_C + c);
        t[ty + i][tx * 2] = v.x;
        t[ty + i][tx * 2 + 1] = v.y;
        *reinterpret_cast<uint32_t*>(xhb + (long)r * SZ_C + c) = pack_hi(v.x, v.y);
        *reinterpret_cast<uint32_t*>(xlb + (long)r * SZ_C + c) = pack_lo(v.x, v.y);
    }
    __syncthreads();
#pragma unroll
    for (int it = 0; it < 2; it++) {
        const int w = it * 256 + tid;
        const int c = w >> 3;
        const int rg = (w & 7) * 4;
        const float v0 = t[rg][c], v1 = t[rg + 1][c];
        const float v2 = t[rg + 2][c], v3 = t[rg + 3][c];
        uint2 hh, ll;
        hh.x = pack_hi(v0, v1); hh.y = pack_hi(v2, v3);
        ll.x = pack_lo(v0, v1); ll.y = pack_lo(v2, v3);
        *reinterpret_cast<uint2*>(xthb + (long)(c0 + c) * SZ_N + n0 + rg) = hh;
        *reinterpret_cast<uint2*>(xtlb + (long)(c0 + c) * SZ_N + n0 + rg) = ll;
    }
}

// ---------------------------------------------------------------------------
// Weight transpose + split
// ---------------------------------------------------------------------------
__global__ void transpose_split(const float* __restrict__ in,
                                bf16* __restrict__ outH, bf16* __restrict__ outL,
                                int R, int Cc)
{
    __shared__ float t[32][33];
    const int c0 = blockIdx.x * 32, r0 = blockIdx.y * 32;
    const int tx = threadIdx.x & 31, ty = threadIdx.x >> 5;

#pragma unroll
    for (int i = 0; i < 32; i += 8) {
        const int r = r0 + ty + i, c = c0 + tx;
        t[ty + i][tx] = (r < R && c < Cc) ? in[(long)r * Cc + c] : 0.f;
    }
    __syncthreads();
#pragma unroll
    for (int i = 0; i < 32; i += 8) {
        const int c = c0 + ty + i, r = r0 + tx;
        if (c < Cc && r < R) {
            const float v = t[tx][ty + i];
            const bf16 h = __float2bfloat16(v);
            outH[(long)c * R + r] = h;
            outL[(long)c * R + r] = __float2bfloat16(v - __bfloat162float(h));
        }
    }
}

// ---------------------------------------------------------------------------
// Register-resident softmax (L=1024)
// ---------------------------------------------------------------------------
__global__ void softmax_emit(const float* __restrict__ s, bf16* __restrict__ ph,
                             bf16* __restrict__ pl)
{
    const long row = blockIdx.x;
    const float4 v = reinterpret_cast<const float4*>(s + row * SZ_N)[threadIdx.x];
    const int tid = threadIdx.x;
    __shared__ float red[8];

    float m = fmaxf(fmaxf(v.x, v.y), fmaxf(v.z, v.w));
#pragma unroll
    for (int o = 16; o; o >>= 1) m = fmaxf(m, __shfl_xor_sync(0xffffffffu, m, o));
    if ((tid & 31) == 0) red[tid >> 5] = m;
    __syncthreads();
    m = red[0];
#pragma unroll
    for (int w = 1; w < 8; w++) m = fmaxf(m, red[w]);

    const float e0 = __expf(v.x - m), e1 = __expf(v.y - m);
    const float e2 = __expf(v.z - m), e3 = __expf(v.w - m);
    float sum = e0 + e1 + e2 + e3;
#pragma unroll
    for (int o = 16; o; o >>= 1) sum += __shfl_xor_sync(0xffffffffu, sum, o);
    __syncthreads();
    if ((tid & 31) == 0) red[tid >> 5] = sum;
    __syncthreads();
    sum = 0.f;
#pragma unroll
    for (int w = 0; w < 8; w++) sum += red[w];
    const float inv = 1.0f / sum;

    const float p0 = e0 * inv, p1 = e1 * inv, p2 = e2 * inv, p3 = e3 * inv;
    uint2 hh, ll;
    hh.x = pack_hi(p0, p1); hh.y = pack_hi(p2, p3);
    ll.x = pack_lo(p0, p1); ll.y = pack_lo(p2, p3);
    reinterpret_cast<uint2*>(ph + row * SZ_N)[tid] = hh;
    reinterpret_cast<uint2*>(pl + row * SZ_N)[tid] = ll;
}

// ---------------------------------------------------------------------------
// Row stats for s2 (L=1280)
// ---------------------------------------------------------------------------
__global__ void rowstats(const float* __restrict__ s2, float* __restrict__ mArr,
                         float* __restrict__ iArr)
{
    const long row = blockIdx.x;
    const float* p = s2 + row * SZ_C;
    const int tid = threadIdx.x;
    __shared__ float red[8];

    const float4 v = reinterpret_cast<const float4*>(p)[tid];
    const float v4 = p[1024 + tid];

    float m = fmaxf(fmaxf(fmaxf(v.x, v.y), fmaxf(v.z, v.w)), v4);
#pragma unroll
    for (int o = 16; o; o >>= 1) m = fmaxf(m, __shfl_xor_sync(0xffffffffu, m, o));
    if ((tid & 31) == 0) red[tid >> 5] = m;
    __syncthreads();
    m = red[0];
#pragma unroll
    for (int w = 1; w < 8; w++) m = fmaxf(m, red[w]);

    float sum = __expf(v.x - m) + __expf(v.y - m) + __expf(v.z - m)
              + __expf(v.w - m) + __expf(v4 - m);
#pragma unroll
    for (int o = 16; o; o >>= 1) sum += __shfl_xor_sync(0xffffffffu, sum, o);
    __syncthreads();
    if ((tid & 31) == 0) red[tid >> 5] = sum;
    __syncthreads();
    sum = 0.f;
#pragma unroll
    for (int w = 0; w < 8; w++) sum += red[w];

    if (tid == 0) { mArr[row] = m; iArr[row] = 1.0f / sum; }
}

__global__ void p2t_emit(const float* __restrict__ s2,
                         const float* __restrict__ mArr,
                         const float* __restrict__ iArr,
                         bf16* __restrict__ th, bf16* __restrict__ tl)
{
    const long r = blockIdx.x;
    const long b = r / SZ_C;
    const float4* p4 = reinterpret_cast<const float4*>(s2 + r * SZ_C);
    const float4* m4 = reinterpret_cast<const float4*>(mArr + b * SZ_C);
    const float4* i4 = reinterpret_cast<const float4*>(iArr + b * SZ_C);
    uint2* oh = reinterpret_cast<uint2*>(th + r * SZ_C);
    uint2* ol = reinterpret_cast<uint2*>(tl + r * SZ_C);
    for (int c4 = threadIdx.x; c4 < SZ_C / 4; c4 += 256) {
        const float4 v = p4[c4];
        const float4 mm = __ldg(m4 + c4);
        const float4 ii = __ldg(i4 + c4);
        const float e0 = __expf(v.x - mm.x) * ii.x;
        const float e1 = __expf(v.y - mm.y) * ii.y;
        const float e2 = __expf(v.z - mm.z) * ii.z;
        const float e3 = __expf(v.w - mm.w) * ii.w;
        uint2 hh, ll;
        hh.x = pack_hi(e0, e1); hh.y = pack_hi(e2, e3);
        ll.x = pack_lo(e0, e1); ll.y = pack_lo(e2, e3);
        oh[c4] = hh;
        ol[c4] = ll;
    }
}

// ---------------------------------------------------------------------------
// kernel_launch
// ---------------------------------------------------------------------------
extern "C" void kernel_launch(void* const* d_in, const int* in_sizes, int n_in,
                              void* d_out, int out_size)
{
    const float* x     = (const float*)d_in[0];
    const float* Wk    = (const float*)d_in[1];
    const float* Wq    = (const float*)d_in[2];
    const float* Wv    = (const float*)d_in[3];
    const float* gamma = (const float*)d_in[4];
    const float* beta  = (const float*)d_in[5];
    float* out = (float*)d_out;

    float *s_, *s2_, *pav_, *m2, *i2;
    bf16 *xh, *xl, *xth, *xtl, *wkqth, *wkqtl, *wvth, *wvtl;
    bf16 *kqh, *kql, *vth, *vtl, *ph, *pl, *p2th, *p2tl;
    cudaGetSymbolAddress((void**)&s_,    g_s);
    cudaGetSymbolAddress((void**)&s2_,   g_s2);
    cudaGetSymbolAddress((void**)&pav_,  g_pav);
    cudaGetSymbolAddress((void**)&m2,    g_m2);
    cudaGetSymbolAddress((void**)&i2,    g_i2);
    cudaGetSymbolAddress((void**)&xh,    g_xh);
    cudaGetSymbolAddress((void**)&xl,    g_xl);
    cudaGetSymbolAddress((void**)&xth,   g_xth);
    cudaGetSymbolAddress((void**)&xtl,   g_xtl);
    cudaGetSymbolAddress((void**)&wkqth, g_wkqth);
    cudaGetSymbolAddress((void**)&wkqtl, g_wkqtl);
    cudaGetSymbolAddress((void**)&wvth,  g_wvth);
    cudaGetSymbolAddress((void**)&wvtl,  g_wvtl);
    cudaGetSymbolAddress((void**)&kqh,   g_kqh);
    cudaGetSymbolAddress((void**)&kql,   g_kql);
    cudaGetSymbolAddress((void**)&vth,   g_vth);
    cudaGetSymbolAddress((void**)&vtl,   g_vtl);
    cudaGetSymbolAddress((void**)&ph,    g_ph);
    cudaGetSymbolAddress((void**)&pl,    g_pl);
    cudaGetSymbolAddress((void**)&p2th,  g_p2th);
    cudaGetSymbolAddress((void**)&p2tl,  g_p2tl);

    constexpr int SMEM  = STAGES * STG;        // 196608
    constexpr int SMEMW = STAGES_W * STG_W;    // 196608
    cudaFuncSetAttribute((const void*)gemm_hl<0, false>,
                         cudaFuncAttributeMaxDynamicSharedMemorySize, SMEM);
    cudaFuncSetAttribute((const void*)gemm_hl<0, true>,
                         cudaFuncAttributeMaxDynamicSharedMemorySize, SMEM);
    cudaFuncSetAttribute((const void*)gemm_hl<1, false>,
                         cudaFuncAttributeMaxDynamicSharedMemorySize, SMEM);
    cudaFuncSetAttribute((const void*)gemm_wide<0>,
                         cudaFuncAttributeMaxDynamicSharedMemorySize, SMEMW);
    cudaFuncSetAttribute((const void*)gemm_wide<1>,
                         cudaFuncAttributeMaxDynamicSharedMemorySize, SMEMW);
    cudaFuncSetAttribute((const void*)gemm_wide<2>,
                         cudaFuncAttributeMaxDynamicSharedMemorySize, SMEMW);

    // ---- operand preparation ----
    xprep<<<dim3(SZ_C / 64, SZ_N / 32, SZ_B), 256>>>(x, xh, xl, xth, xtl);
    transpose_split<<<dim3(5, 40, 1), 256>>>(Wk, wkqth, wkqtl, SZ_C, SZ_D);
    transpose_split<<<dim3(5, 40, 1), 256>>>(
        Wq, wkqth + (size_t)SZ_D * SZ_C, wkqtl + (size_t)SZ_D * SZ_C, SZ_C, SZ_D);
    transpose_split<<<dim3(40, 40, 1), 256>>>(Wv, wvth, wvtl, SZ_C, SZ_C);

    // ---- fused kq projection (narrow, N=320) ----
    gemm_hl<1, false><<<dim3(3, 128, 1), 256, SMEM>>>(
        xh, xl, wkqth, wkqtl, nullptr, kqh, kql,
        2 * SZ_D, SZ_C, SZ_C, SZ_C, 2 * SZ_D, 0, 0, 0);

    // ---- vT = Wv^T @ x^T (wide: M=1280, N=16384) ----
    gemm_wide<1><<<dim3(64, 10, 1), 256, SMEMW>>>(
        wvth, wvtl, xh, xl, nullptr, vth, vtl, nullptr, nullptr, nullptr, nullptr,
        SZ_C, SZ_C, SZ_C, SZ_BN, 0, 0, 0);

    // ---- s = k @ q^T (narrow, K=160) ----
    gemm_hl<0, false><<<dim3(8, 8, SZ_B), 256, SMEM>>>(
        kqh, kql, kqh + SZ_D, kql + SZ_D, s_, nullptr, nullptr,
        SZ_N, SZ_D, 2 * SZ_D, 2 * SZ_D, SZ_N,
        (long)SZ_N * 2 * SZ_D, (long)SZ_N * 2 * SZ_D, (long)SZ_N * SZ_N);
    softmax_emit<<<SZ_B * SZ_N, 256>>>(s_, ph, pl);

    // ---- pav = p @ v (wide: N=1280, K=1024) ----
    gemm_wide<0><<<dim3(5, 8, SZ_B), 256, SMEMW>>>(
        ph, pl, vth, vtl, pav_, nullptr, nullptr, nullptr, nullptr, nullptr, nullptr,
        SZ_N, SZ_N, SZ_BN, SZ_C,
        (long)SZ_N * SZ_N, (long)SZ_N, (long)SZ_N * SZ_C);

    // ---- s2 = x^T @ x (narrow triangular) -> stats -> p2T ----
    gemm_hl<0, true><<<dim3(55, 1, SZ_B), 256, SMEM>>>(
        xth, xtl, xth, xtl, s2_, nullptr, nullptr,
        SZ_C, SZ_N, SZ_N, SZ_N, SZ_C,
        (long)SZ_C * SZ_N, (long)SZ_C * SZ_N, (long)SZ_C * SZ_C);
    rowstats<<<SZ_B * SZ_C, 256>>>(s2_, m2, i2);
    p2t_emit<<<SZ_B * SZ_C, 256>>>(s2_, m2, i2, p2th, p2tl);

    // ---- final: out = gamma*pav + beta*(x @ p2) + 2*x (wide, fused) ----
    gemm_wide<2><<<dim3(5, 8, SZ_B), 256, SMEMW>>>(
        xh, xl, p2th, p2tl, out, nullptr, nullptr, pav_, x, gamma, beta,
        SZ_C, SZ_C, SZ_C, SZ_C,
        (long)SZ_N * SZ_C, (long)SZ_C * SZ_C, (long)SZ_N * SZ_C);
}